// round 16
// baseline (speedup 1.0000x reference)
#include <cuda_runtime.h>
#include <cuda_fp16.h>
#include <cstdint>

#define DI __device__ __forceinline__

DI uint32_t h2pack(float lo, float hi){ uint32_t r;
    asm("cvt.rn.f16x2.f32 %0, %1, %2;":"=r"(r):"f"(hi),"f"(lo)); return r; }
DI float ex2(float x){ float y; asm("ex2.approx.f32 %0, %1;":"=f"(y):"f"(x)); return y; }
DI void mma16(float* c, const uint32_t* a, uint32_t b0, uint32_t b1){
    asm volatile("mma.sync.aligned.m16n8k16.row.col.f32.f16.f16.f32 "
        "{%0,%1,%2,%3}, {%4,%5,%6,%7}, {%8,%9}, {%0,%1,%2,%3};"
        : "+f"(c[0]),"+f"(c[1]),"+f"(c[2]),"+f"(c[3])
        : "r"(a[0]),"r"(a[1]),"r"(a[2]),"r"(a[3]),"r"(b0),"r"(b1));
}
DI void ldsm4(uint32_t& r0, uint32_t& r1, uint32_t& r2, uint32_t& r3, uint32_t a){
    asm volatile("ldmatrix.sync.aligned.m8n8.x4.shared.b16 {%0,%1,%2,%3}, [%4];"
        : "=r"(r0),"=r"(r1),"=r"(r2),"=r"(r3) : "r"(a));
}
DI uint32_t smem_u32(const void* p){ uint32_t a;
    asm("{ .reg .u64 t; cvta.to.shared.u64 t, %1; cvt.u32.u64 %0, t; }":"=r"(a):"l"(p)); return a; }
DI void cpa16(uint32_t dst, const void* src){
    asm volatile("cp.async.cg.shared.global [%0], [%1], 16;"::"r"(dst),"l"(src)); }
DI void cpcommit(){ asm volatile("cp.async.commit_group;":::"memory"); }
template<int N> DI void cpwaitg(){ asm volatile("cp.async.wait_group %0;"::"n"(N):"memory"); }

namespace {
constexpr int Nn = 1024, Cc = 128, QT = 64, KT = 64;
constexpr float SCALEQ = 0.08838834764831845f * 1.4426950408889634f;  // 1/sqrt(C) * log2(e)
}

__device__ __half g_qh[64*1024*128];
__device__ __half g_kh[64*1024*128];
__device__ __half g_vt[64*128*1024];   // channel-major [bh][ch][n]

// ---------------- kernel 1: Lorentz transforms -> fp16; V transposed in registers ----------------
__global__ __launch_bounds__(256)
void ipa_prep(const float* __restrict__ gq, const float* __restrict__ gk,
              const float* __restrict__ gv, const float* __restrict__ gL)
{
    const int tid = threadIdx.x, wid = tid>>5, lane = tid&31;
    const int bh = blockIdx.x >> 3;
    const int n0 = (blockIdx.x & 7) * 128;
    const int b  = bh >> 3;
    const int nw0 = n0 + wid*16;
    const int ch = lane*4;

    uint32_t vr0[16], vr1[16];   // fp16x2 V results per token (ch, ch+1) / (ch+2, ch+3)

    #pragma unroll
    for (int tk = 0; tk < 16; tk++){
        const int n = nw0 + tk;
        const float* Lp = gL + ((size_t)(b*1024 + n))*16;
        float4 L0 = __ldg((const float4*)Lp);
        float4 L1 = __ldg((const float4*)(Lp+4));
        float4 L2 = __ldg((const float4*)(Lp+8));
        float4 L3 = __ldg((const float4*)(Lp+12));
        float Lv[16] = {L0.x,L0.y,L0.z,L0.w, L1.x,L1.y,L1.z,L1.w,
                        L2.x,L2.y,L2.z,L2.w, L3.x,L3.y,L3.z,L3.w};
        float kM[4][4], iM[4][4];
        #pragma unroll
        for (int i = 0; i < 4; i++)
            #pragma unroll
            for (int j = 0; j < 4; j++){
                float sj = (j==0)?1.f:-1.f, si = (i==0)?1.f:-1.f;
                kM[i][j] = sj * Lv[j*4+i];      // (L^T eta)
                iM[i][j] = si * kM[i][j];       // (eta L^T eta)
            }

        const size_t base = ((size_t)(bh*1024 + n))*128 + ch;
        float4 xq = __ldg((const float4*)(gq + base));
        float4 xk = __ldg((const float4*)(gk + base));
        float4 xv = __ldg((const float4*)(gv + base));
        float4 yq, yk, yv;
        if (lane < 2){ yq = xq; yk = xk; yv = xv; }
        else {
            yq.x = iM[0][0]*xq.x+iM[0][1]*xq.y+iM[0][2]*xq.z+iM[0][3]*xq.w;
            yq.y = iM[1][0]*xq.x+iM[1][1]*xq.y+iM[1][2]*xq.z+iM[1][3]*xq.w;
            yq.z = iM[2][0]*xq.x+iM[2][1]*xq.y+iM[2][2]*xq.z+iM[2][3]*xq.w;
            yq.w = iM[3][0]*xq.x+iM[3][1]*xq.y+iM[3][2]*xq.z+iM[3][3]*xq.w;
            yk.x = kM[0][0]*xk.x+kM[0][1]*xk.y+kM[0][2]*xk.z+kM[0][3]*xk.w;
            yk.y = kM[1][0]*xk.x+kM[1][1]*xk.y+kM[1][2]*xk.z+kM[1][3]*xk.w;
            yk.z = kM[2][0]*xk.x+kM[2][1]*xk.y+kM[2][2]*xk.z+kM[2][3]*xk.w;
            yk.w = kM[3][0]*xk.x+kM[3][1]*xk.y+kM[3][2]*xk.z+kM[3][3]*xk.w;
            yv.x = iM[0][0]*xv.x+iM[0][1]*xv.y+iM[0][2]*xv.z+iM[0][3]*xv.w;
            yv.y = iM[1][0]*xv.x+iM[1][1]*xv.y+iM[1][2]*xv.z+iM[1][3]*xv.w;
            yv.z = iM[2][0]*xv.x+iM[2][1]*xv.y+iM[2][2]*xv.z+iM[2][3]*xv.w;
            yv.w = iM[3][0]*xv.x+iM[3][1]*xv.y+iM[3][2]*xv.z+iM[3][3]*xv.w;
        }
        uint2 uq = make_uint2(h2pack(yq.x*SCALEQ, yq.y*SCALEQ),
                              h2pack(yq.z*SCALEQ, yq.w*SCALEQ));
        uint2 uk = make_uint2(h2pack(yk.x, yk.y), h2pack(yk.z, yk.w));
        *(uint2*)((__half*)g_qh + base) = uq;
        *(uint2*)((__half*)g_kh + base) = uk;
        vr0[tk] = h2pack(yv.x, yv.y);
        vr1[tk] = h2pack(yv.z, yv.w);
    }

    // ---- V writeout: repack lo/hi halves per channel, store channel-major rows ----
    {
        __half* vbase = (__half*)g_vt + ((size_t)(bh*128 + ch))*1024 + nw0;
        uint32_t w[8];
        // channel ch+0: lo halves of vr0
        #pragma unroll
        for (int t = 0; t < 8; t++) w[t] = __byte_perm(vr0[2*t], vr0[2*t+1], 0x5410);
        *(uint4*)(vbase)     = make_uint4(w[0],w[1],w[2],w[3]);
        *(uint4*)(vbase + 8) = make_uint4(w[4],w[5],w[6],w[7]);
        // channel ch+1: hi halves of vr0
        #pragma unroll
        for (int t = 0; t < 8; t++) w[t] = __byte_perm(vr0[2*t], vr0[2*t+1], 0x7632);
        *(uint4*)(vbase + 1024)     = make_uint4(w[0],w[1],w[2],w[3]);
        *(uint4*)(vbase + 1024 + 8) = make_uint4(w[4],w[5],w[6],w[7]);
        // channel ch+2: lo halves of vr1
        #pragma unroll
        for (int t = 0; t < 8; t++) w[t] = __byte_perm(vr1[2*t], vr1[2*t+1], 0x5410);
        *(uint4*)(vbase + 2048)     = make_uint4(w[0],w[1],w[2],w[3]);
        *(uint4*)(vbase + 2048 + 8) = make_uint4(w[4],w[5],w[6],w[7]);
        // channel ch+3: hi halves of vr1
        #pragma unroll
        for (int t = 0; t < 8; t++) w[t] = __byte_perm(vr1[2*t], vr1[2*t+1], 0x7632);
        *(uint4*)(vbase + 3072)     = make_uint4(w[0],w[1],w[2],w[3]);
        *(uint4*)(vbase + 3072 + 8) = make_uint4(w[4],w[5],w[6],w[7]);
    }
}

// ---------------- kernel 2: fp16 flash attention (round-14 champion, verbatim) ----------------
__global__ __launch_bounds__(128, 3)
void ipa_fa(const float* __restrict__ gL, float* __restrict__ gout)
{
    extern __shared__ __half smh[];              // 65536 B
    const uint32_t SB = smem_u32(smh);
    const uint32_t* W = (const uint32_t*)smh;

    const int tid = threadIdx.x, wid = tid>>5, lane = tid&31;
    const int gid = lane>>2, t4 = lane&3;
    const int bh = blockIdx.y, b = bh>>3;
    const int q0 = blockIdx.x * QT;

    const __half* qh = g_qh + (size_t)bh*Nn*Cc;
    const __half* kh = g_kh + (size_t)bh*Nn*Cc;
    const __half* vt = g_vt + (size_t)bh*Cc*Nn;

    const int mh = (lane >> 4) & 1;
    const int mc = (lane >> 3) & 1;
    const int r8 = lane & 7;

    // ---- prologue: Q -> buf1 K area; tile0 -> buf0 ----
    {
        #pragma unroll
        for (int i = 0; i < 8; i++){
            int idx = tid + 128*i;
            int row = idx >> 4, c = idx & 15;
            uint32_t cp = (uint32_t)(c ^ (row & 7));
            cpa16(SB + 32768u + (uint32_t)row*256u + cp*16u,
                  qh + (size_t)(q0 + row)*128 + c*8);
        }
        cpcommit();
        #pragma unroll
        for (int i = 0; i < 8; i++){
            int idx = tid + 128*i;
            int row = idx >> 4, c = idx & 15;
            uint32_t cp = (uint32_t)(c ^ (row & 7));
            cpa16(SB + (uint32_t)row*256u + cp*16u, kh + (size_t)row*128 + c*8);
        }
        #pragma unroll
        for (int i = 0; i < 8; i++){
            int idx = tid + 128*i;
            int ch = idx >> 3, c = idx & 7;
            uint32_t cp = (uint32_t)(c ^ (ch & 7));
            cpa16(SB + 16384u + (uint32_t)ch*128u + cp*16u,
                  vt + (size_t)ch*1024 + c*8);
        }
        cpcommit();
        cpwaitg<1>();          // Q group retired
        __syncthreads();       // all threads' Q writes visible
    }

    // ---- Q fragments -> registers ----
    const int srow = wid*16 + gid;
    uint32_t qa[8][4];
    {
        const uint32_t* Wq = W + 8192;
        const uint32_t xr = 4u*(uint32_t)(srow & 7);
        const uint32_t* r0 = Wq + srow*64;
        const uint32_t* r1 = Wq + (srow+8)*64;
        #pragma unroll
        for (int k16 = 0; k16 < 8; k16++){
            uint32_t c0 = (uint32_t)(k16*8 + t4) ^ xr;
            uint32_t c1 = (uint32_t)(k16*8 + t4 + 4) ^ xr;
            qa[k16][0]=r0[c0]; qa[k16][1]=r1[c0]; qa[k16][2]=r0[c1]; qa[k16][3]=r1[c1];
        }
    }

    float l0 = 0.f, l1 = 0.f;
    float o[16][4];
    #pragma unroll
    for (int cb = 0; cb < 16; cb++){ o[cb][0]=0.f; o[cb][1]=0.f; o[cb][2]=0.f; o[cb][3]=0.f; }

    uint32_t krow[4], vrow[8];
    #pragma unroll
    for (int j = 0; j < 4; j++) krow[j] = (uint32_t)((16*j + mh*8 + r8) * 256);
    #pragma unroll
    for (int j = 0; j < 8; j++) vrow[j] = (uint32_t)((16*j + mh*8 + r8) * 128);

    for (int t = 0; t < Nn/KT; t++){
        const int buf = t & 1;
        cpwaitg<0>();          // tile t arrived
        __syncthreads();       // cross-thread visibility; tile t-1 reads done
        if (t + 1 < Nn/KT){    // prefetch t+1 into buffer freed by t-1
            const int nb2 = (t+1) & 1;
            const __half* kt = kh + (size_t)((t+1)*KT)*128;
            const __half* vp = vt + (size_t)((t+1)*KT);
            #pragma unroll
            for (int i = 0; i < 8; i++){
                int idx = tid + 128*i;
                int row = idx >> 4, c = idx & 15;
                uint32_t cp = (uint32_t)(c ^ (row & 7));
                cpa16(SB + (uint32_t)nb2*32768u + (uint32_t)row*256u + cp*16u,
                      kt + (size_t)row*128 + c*8);
            }
            #pragma unroll
            for (int i = 0; i < 8; i++){
                int idx = tid + 128*i;
                int ch = idx >> 3, c = idx & 7;
                uint32_t cp = (uint32_t)(c ^ (ch & 7));
                cpa16(SB + (uint32_t)nb2*32768u + 16384u + (uint32_t)ch*128u + cp*16u,
                      vp + (size_t)ch*1024 + c*8);
            }
            cpcommit();
        }

        // ---- S = Q K^T (ldmatrix B fragments) ----
        const uint32_t Kb = SB + (uint32_t)buf*32768u;
        float c[8][4];
        #pragma unroll
        for (int nb = 0; nb < 8; nb++){ c[nb][0]=0.f; c[nb][1]=0.f; c[nb][2]=0.f; c[nb][3]=0.f; }
        #pragma unroll
        for (int k16 = 0; k16 < 8; k16++){
            uint32_t cx = (uint32_t)(((2*k16 + mc) ^ r8) << 4);
            #pragma unroll
            for (int j = 0; j < 4; j++){
                uint32_t b0, b1, b2, b3;
                ldsm4(b0, b1, b2, b3, Kb + krow[j] + cx);
                mma16(c[2*j],   qa[k16], b0, b1);
                mma16(c[2*j+1], qa[k16], b2, b3);
            }
        }

        // ---- softmax: p = exp2(s), bias-free (2^-M folds out of O/l) ----
        float s0 = 0.f, s1 = 0.f;
        #pragma unroll
        for (int nb = 0; nb < 8; nb++){
            c[nb][0] = ex2(c[nb][0]);
            c[nb][1] = ex2(c[nb][1]);
            c[nb][2] = ex2(c[nb][2]);
            c[nb][3] = ex2(c[nb][3]);
            s0 += c[nb][0] + c[nb][1];
            s1 += c[nb][2] + c[nb][3];
        }
        l0 += s0; l1 += s1;

        // ---- O += P V (P packed from C fragments; ldmatrix V) ----
        const uint32_t Vb = Kb + 16384u;
        #pragma unroll
        for (int k16 = 0; k16 < 4; k16++){
            uint32_t pa[4] = { h2pack(c[2*k16][0],   c[2*k16][1]),
                               h2pack(c[2*k16][2],   c[2*k16][3]),
                               h2pack(c[2*k16+1][0], c[2*k16+1][1]),
                               h2pack(c[2*k16+1][2], c[2*k16+1][3]) };
            uint32_t cx = (uint32_t)(((2*k16 + mc) ^ r8) << 4);
            #pragma unroll
            for (int j = 0; j < 8; j++){
                uint32_t b0, b1, b2, b3;
                ldsm4(b0, b1, b2, b3, Vb + vrow[j] + cx);
                mma16(o[2*j],   pa, b0, b1);
                mma16(o[2*j+1], pa, b2, b3);
            }
        }
    }

    // ---- final l reduction across the quad ----
    l0 += __shfl_xor_sync(0xffffffffu, l0, 1);
    l0 += __shfl_xor_sync(0xffffffffu, l0, 2);
    l1 += __shfl_xor_sync(0xffffffffu, l1, 1);
    l1 += __shfl_xor_sync(0xffffffffu, l1, 2);

    // ---- stage normalized O (fp32, stride 132) and epilogue ----
    __syncthreads();
    float* Of = (float*)smh;
    const float inv0 = 1.f/l0, inv1 = 1.f/l1;
    #pragma unroll
    for (int cb = 0; cb < 16; cb++){
        *(float2*)(Of + srow*132 + cb*8 + 2*t4)     = make_float2(o[cb][0]*inv0, o[cb][1]*inv0);
        *(float2*)(Of + (srow+8)*132 + cb*8 + 2*t4) = make_float2(o[cb][2]*inv1, o[cb][3]*inv1);
    }
    __syncthreads();
    {
        const int row = tid>>1, half_ = tid&1;
        const int rowg = q0 + row;
        const float* Lp = gL + ((size_t)(b*1024) + rowg)*16;
        float Lq[16];
        #pragma unroll
        for (int i = 0; i < 4; i++){ float4 t4v = *(const float4*)(Lp + i*4);
            Lq[i*4+0]=t4v.x; Lq[i*4+1]=t4v.y; Lq[i*4+2]=t4v.z; Lq[i*4+3]=t4v.w; }
        const float* sp = Of + row*132 + half_*64;
        float* orow = gout + ((size_t)bh*Nn + rowg)*Cc + half_*64;
        #pragma unroll
        for (int g = 0; g < 16; g++){
            const int ch = half_*64 + g*4;
            float4 x = *(const float4*)(sp + g*4);
            float4 y;
            if (ch < 8) y = x;
            else {
                y.x = Lq[ 0]*x.x + Lq[ 1]*x.y + Lq[ 2]*x.z + Lq[ 3]*x.w;
                y.y = Lq[ 4]*x.x + Lq[ 5]*x.y + Lq[ 6]*x.z + Lq[ 7]*x.w;
                y.z = Lq[ 8]*x.x + Lq[ 9]*x.y + Lq[10]*x.z + Lq[11]*x.w;
                y.w = Lq[12]*x.x + Lq[13]*x.y + Lq[14]*x.z + Lq[15]*x.w;
            }
            *(float4*)(orow + g*4) = y;
        }
    }
}

extern "C" void kernel_launch(void* const* d_in, const int* in_sizes, int n_in,
                              void* d_out, int out_size)
{
    const float* q = (const float*)d_in[0];
    const float* k = (const float*)d_in[1];
    const float* v = (const float*)d_in[2];
    const float* L = (const float*)d_in[3];
    float* out = (float*)d_out;

    ipa_prep<<<512, 256>>>(q, k, v, L);

    cudaFuncSetAttribute(ipa_fa, cudaFuncAttributeMaxDynamicSharedMemorySize, 65536);
    dim3 grid(Nn/QT, 64);
    ipa_fa<<<grid, 128, 65536>>>(L, out);
}

// round 17
// speedup vs baseline: 1.0623x; 1.0623x over previous
#include <cuda_runtime.h>
#include <cuda_fp16.h>
#include <cstdint>

#define DI __device__ __forceinline__

DI uint32_t h2pack(float lo, float hi){ uint32_t r;
    asm("cvt.rn.f16x2.f32 %0, %1, %2;":"=r"(r):"f"(hi),"f"(lo)); return r; }
DI float ex2(float x){ float y; asm("ex2.approx.f32 %0, %1;":"=f"(y):"f"(x)); return y; }
DI void mma16(float* c, const uint32_t* a, uint32_t b0, uint32_t b1){
    asm volatile("mma.sync.aligned.m16n8k16.row.col.f32.f16.f16.f32 "
        "{%0,%1,%2,%3}, {%4,%5,%6,%7}, {%8,%9}, {%0,%1,%2,%3};"
        : "+f"(c[0]),"+f"(c[1]),"+f"(c[2]),"+f"(c[3])
        : "r"(a[0]),"r"(a[1]),"r"(a[2]),"r"(a[3]),"r"(b0),"r"(b1));
}
DI void ldsm4(uint32_t& r0, uint32_t& r1, uint32_t& r2, uint32_t& r3, uint32_t a){
    asm volatile("ldmatrix.sync.aligned.m8n8.x4.shared.b16 {%0,%1,%2,%3}, [%4];"
        : "=r"(r0),"=r"(r1),"=r"(r2),"=r"(r3) : "r"(a));
}
DI uint32_t smem_u32(const void* p){ uint32_t a;
    asm("{ .reg .u64 t; cvta.to.shared.u64 t, %1; cvt.u32.u64 %0, t; }":"=r"(a):"l"(p)); return a; }
DI void cpa16(uint32_t dst, const void* src){
    asm volatile("cp.async.cg.shared.global [%0], [%1], 16;"::"r"(dst),"l"(src)); }
DI void cpcommit(){ asm volatile("cp.async.commit_group;":::"memory"); }
template<int N> DI void cpwaitg(){ asm volatile("cp.async.wait_group %0;"::"n"(N):"memory"); }

namespace {
constexpr int Nn = 1024, Cc = 128, QT = 64, KT = 64;
constexpr float SCALEQ = 0.08838834764831845f * 1.4426950408889634f;  // 1/sqrt(C) * log2(e)
}

__device__ __half g_qh[64*1024*128];
__device__ __half g_kh[64*1024*128];
__device__ __half g_vt[64*128*1024];   // channel-major [bh][ch][n]

// ---------------- kernel 1: Lorentz transforms -> fp16; V reg-transposed in 2 half-batches ----------------
__global__ __launch_bounds__(256)
void ipa_prep(const float* __restrict__ gq, const float* __restrict__ gk,
              const float* __restrict__ gv, const float* __restrict__ gL)
{
    const int tid = threadIdx.x, wid = tid>>5, lane = tid&31;
    const int bh = blockIdx.x >> 3;
    const int n0 = (blockIdx.x & 7) * 128;
    const int b  = bh >> 3;
    const int nw0 = n0 + wid*16;
    const int ch = lane*4;
    __half* vbase = (__half*)g_vt + ((size_t)(bh*128 + ch))*1024 + nw0;

    #pragma unroll 1
    for (int hb = 0; hb < 2; hb++){          // two half-batches of 8 tokens
        uint32_t vr0[8], vr1[8];             // only 16 live V regs
        #pragma unroll
        for (int tk = 0; tk < 8; tk++){
            const int n = nw0 + hb*8 + tk;
            const float* Lp = gL + ((size_t)(b*1024 + n))*16;
            float4 L0 = __ldg((const float4*)Lp);
            float4 L1 = __ldg((const float4*)(Lp+4));
            float4 L2 = __ldg((const float4*)(Lp+8));
            float4 L3 = __ldg((const float4*)(Lp+12));
            float Lv[16] = {L0.x,L0.y,L0.z,L0.w, L1.x,L1.y,L1.z,L1.w,
                            L2.x,L2.y,L2.z,L2.w, L3.x,L3.y,L3.z,L3.w};
            float kM[4][4], iM[4][4];
            #pragma unroll
            for (int i = 0; i < 4; i++)
                #pragma unroll
                for (int j = 0; j < 4; j++){
                    float sj = (j==0)?1.f:-1.f, si = (i==0)?1.f:-1.f;
                    kM[i][j] = sj * Lv[j*4+i];      // (L^T eta)
                    iM[i][j] = si * kM[i][j];       // (eta L^T eta)
                }

            const size_t base = ((size_t)(bh*1024 + n))*128 + ch;
            float4 xq = __ldg((const float4*)(gq + base));
            float4 xk = __ldg((const float4*)(gk + base));
            float4 xv = __ldg((const float4*)(gv + base));
            float4 yq, yk, yv;
            if (lane < 2){ yq = xq; yk = xk; yv = xv; }
            else {
                yq.x = iM[0][0]*xq.x+iM[0][1]*xq.y+iM[0][2]*xq.z+iM[0][3]*xq.w;
                yq.y = iM[1][0]*xq.x+iM[1][1]*xq.y+iM[1][2]*xq.z+iM[1][3]*xq.w;
                yq.z = iM[2][0]*xq.x+iM[2][1]*xq.y+iM[2][2]*xq.z+iM[2][3]*xq.w;
                yq.w = iM[3][0]*xq.x+iM[3][1]*xq.y+iM[3][2]*xq.z+iM[3][3]*xq.w;
                yk.x = kM[0][0]*xk.x+kM[0][1]*xk.y+kM[0][2]*xk.z+kM[0][3]*xk.w;
                yk.y = kM[1][0]*xk.x+kM[1][1]*xk.y+kM[1][2]*xk.z+kM[1][3]*xk.w;
                yk.z = kM[2][0]*xk.x+kM[2][1]*xk.y+kM[2][2]*xk.z+kM[2][3]*xk.w;
                yk.w = kM[3][0]*xk.x+kM[3][1]*xk.y+kM[3][2]*xk.z+kM[3][3]*xk.w;
                yv.x = iM[0][0]*xv.x+iM[0][1]*xv.y+iM[0][2]*xv.z+iM[0][3]*xv.w;
                yv.y = iM[1][0]*xv.x+iM[1][1]*xv.y+iM[1][2]*xv.z+iM[1][3]*xv.w;
                yv.z = iM[2][0]*xv.x+iM[2][1]*xv.y+iM[2][2]*xv.z+iM[2][3]*xv.w;
                yv.w = iM[3][0]*xv.x+iM[3][1]*xv.y+iM[3][2]*xv.z+iM[3][3]*xv.w;
            }
            uint2 uq = make_uint2(h2pack(yq.x*SCALEQ, yq.y*SCALEQ),
                                  h2pack(yq.z*SCALEQ, yq.w*SCALEQ));
            uint2 uk = make_uint2(h2pack(yk.x, yk.y), h2pack(yk.z, yk.w));
            *(uint2*)((__half*)g_qh + base) = uq;
            *(uint2*)((__half*)g_kh + base) = uk;
            vr0[tk] = h2pack(yv.x, yv.y);
            vr1[tk] = h2pack(yv.z, yv.w);
        }
        // ---- V writeout for this half: 16B per channel (half of a 32B sector) ----
        {
            uint32_t w[4];
            #pragma unroll
            for (int t = 0; t < 4; t++) w[t] = __byte_perm(vr0[2*t], vr0[2*t+1], 0x5410);
            *(uint4*)(vbase + hb*8) = make_uint4(w[0],w[1],w[2],w[3]);
            #pragma unroll
            for (int t = 0; t < 4; t++) w[t] = __byte_perm(vr0[2*t], vr0[2*t+1], 0x7632);
            *(uint4*)(vbase + 1024 + hb*8) = make_uint4(w[0],w[1],w[2],w[3]);
            #pragma unroll
            for (int t = 0; t < 4; t++) w[t] = __byte_perm(vr1[2*t], vr1[2*t+1], 0x5410);
            *(uint4*)(vbase + 2048 + hb*8) = make_uint4(w[0],w[1],w[2],w[3]);
            #pragma unroll
            for (int t = 0; t < 4; t++) w[t] = __byte_perm(vr1[2*t], vr1[2*t+1], 0x7632);
            *(uint4*)(vbase + 3072 + hb*8) = make_uint4(w[0],w[1],w[2],w[3]);
        }
    }
}

// ---------------- kernel 2: fp16 flash attention (round-14 champion, verbatim) ----------------
__global__ __launch_bounds__(128, 3)
void ipa_fa(const float* __restrict__ gL, float* __restrict__ gout)
{
    extern __shared__ __half smh[];              // 65536 B
    const uint32_t SB = smem_u32(smh);
    const uint32_t* W = (const uint32_t*)smh;

    const int tid = threadIdx.x, wid = tid>>5, lane = tid&31;
    const int gid = lane>>2, t4 = lane&3;
    const int bh = blockIdx.y, b = bh>>3;
    const int q0 = blockIdx.x * QT;

    const __half* qh = g_qh + (size_t)bh*Nn*Cc;
    const __half* kh = g_kh + (size_t)bh*Nn*Cc;
    const __half* vt = g_vt + (size_t)bh*Cc*Nn;

    const int mh = (lane >> 4) & 1;
    const int mc = (lane >> 3) & 1;
    const int r8 = lane & 7;

    // ---- prologue: Q -> buf1 K area; tile0 -> buf0 ----
    {
        #pragma unroll
        for (int i = 0; i < 8; i++){
            int idx = tid + 128*i;
            int row = idx >> 4, c = idx & 15;
            uint32_t cp = (uint32_t)(c ^ (row & 7));
            cpa16(SB + 32768u + (uint32_t)row*256u + cp*16u,
                  qh + (size_t)(q0 + row)*128 + c*8);
        }
        cpcommit();
        #pragma unroll
        for (int i = 0; i < 8; i++){
            int idx = tid + 128*i;
            int row = idx >> 4, c = idx & 15;
            uint32_t cp = (uint32_t)(c ^ (row & 7));
            cpa16(SB + (uint32_t)row*256u + cp*16u, kh + (size_t)row*128 + c*8);
        }
        #pragma unroll
        for (int i = 0; i < 8; i++){
            int idx = tid + 128*i;
            int ch = idx >> 3, c = idx & 7;
            uint32_t cp = (uint32_t)(c ^ (ch & 7));
            cpa16(SB + 16384u + (uint32_t)ch*128u + cp*16u,
                  vt + (size_t)ch*1024 + c*8);
        }
        cpcommit();
        cpwaitg<1>();          // Q group retired
        __syncthreads();       // all threads' Q writes visible
    }

    // ---- Q fragments -> registers ----
    const int srow = wid*16 + gid;
    uint32_t qa[8][4];
    {
        const uint32_t* Wq = W + 8192;
        const uint32_t xr = 4u*(uint32_t)(srow & 7);
        const uint32_t* r0 = Wq + srow*64;
        const uint32_t* r1 = Wq + (srow+8)*64;
        #pragma unroll
        for (int k16 = 0; k16 < 8; k16++){
            uint32_t c0 = (uint32_t)(k16*8 + t4) ^ xr;
            uint32_t c1 = (uint32_t)(k16*8 + t4 + 4) ^ xr;
            qa[k16][0]=r0[c0]; qa[k16][1]=r1[c0]; qa[k16][2]=r0[c1]; qa[k16][3]=r1[c1];
        }
    }

    float l0 = 0.f, l1 = 0.f;
    float o[16][4];
    #pragma unroll
    for (int cb = 0; cb < 16; cb++){ o[cb][0]=0.f; o[cb][1]=0.f; o[cb][2]=0.f; o[cb][3]=0.f; }

    uint32_t krow[4], vrow[8];
    #pragma unroll
    for (int j = 0; j < 4; j++) krow[j] = (uint32_t)((16*j + mh*8 + r8) * 256);
    #pragma unroll
    for (int j = 0; j < 8; j++) vrow[j] = (uint32_t)((16*j + mh*8 + r8) * 128);

    for (int t = 0; t < Nn/KT; t++){
        const int buf = t & 1;
        cpwaitg<0>();          // tile t arrived
        __syncthreads();       // cross-thread visibility; tile t-1 reads done
        if (t + 1 < Nn/KT){    // prefetch t+1 into buffer freed by t-1
            const int nb2 = (t+1) & 1;
            const __half* kt = kh + (size_t)((t+1)*KT)*128;
            const __half* vp = vt + (size_t)((t+1)*KT);
            #pragma unroll
            for (int i = 0; i < 8; i++){
                int idx = tid + 128*i;
                int row = idx >> 4, c = idx & 15;
                uint32_t cp = (uint32_t)(c ^ (row & 7));
                cpa16(SB + (uint32_t)nb2*32768u + (uint32_t)row*256u + cp*16u,
                      kt + (size_t)row*128 + c*8);
            }
            #pragma unroll
            for (int i = 0; i < 8; i++){
                int idx = tid + 128*i;
                int ch = idx >> 3, c = idx & 7;
                uint32_t cp = (uint32_t)(c ^ (ch & 7));
                cpa16(SB + (uint32_t)nb2*32768u + 16384u + (uint32_t)ch*128u + cp*16u,
                      vp + (size_t)ch*1024 + c*8);
            }
            cpcommit();
        }

        // ---- S = Q K^T (ldmatrix B fragments) ----
        const uint32_t Kb = SB + (uint32_t)buf*32768u;
        float c[8][4];
        #pragma unroll
        for (int nb = 0; nb < 8; nb++){ c[nb][0]=0.f; c[nb][1]=0.f; c[nb][2]=0.f; c[nb][3]=0.f; }
        #pragma unroll
        for (int k16 = 0; k16 < 8; k16++){
            uint32_t cx = (uint32_t)(((2*k16 + mc) ^ r8) << 4);
            #pragma unroll
            for (int j = 0; j < 4; j++){
                uint32_t b0, b1, b2, b3;
                ldsm4(b0, b1, b2, b3, Kb + krow[j] + cx);
                mma16(c[2*j],   qa[k16], b0, b1);
                mma16(c[2*j+1], qa[k16], b2, b3);
            }
        }

        // ---- softmax: p = exp2(s), bias-free (2^-M folds out of O/l) ----
        float s0 = 0.f, s1 = 0.f;
        #pragma unroll
        for (int nb = 0; nb < 8; nb++){
            c[nb][0] = ex2(c[nb][0]);
            c[nb][1] = ex2(c[nb][1]);
            c[nb][2] = ex2(c[nb][2]);
            c[nb][3] = ex2(c[nb][3]);
            s0 += c[nb][0] + c[nb][1];
            s1 += c[nb][2] + c[nb][3];
        }
        l0 += s0; l1 += s1;

        // ---- O += P V (P packed from C fragments; ldmatrix V) ----
        const uint32_t Vb = Kb + 16384u;
        #pragma unroll
        for (int k16 = 0; k16 < 4; k16++){
            uint32_t pa[4] = { h2pack(c[2*k16][0],   c[2*k16][1]),
                               h2pack(c[2*k16][2],   c[2*k16][3]),
                               h2pack(c[2*k16+1][0], c[2*k16+1][1]),
                               h2pack(c[2*k16+1][2], c[2*k16+1][3]) };
            uint32_t cx = (uint32_t)(((2*k16 + mc) ^ r8) << 4);
            #pragma unroll
            for (int j = 0; j < 8; j++){
                uint32_t b0, b1, b2, b3;
                ldsm4(b0, b1, b2, b3, Vb + vrow[j] + cx);
                mma16(o[2*j],   pa, b0, b1);
                mma16(o[2*j+1], pa, b2, b3);
            }
        }
    }

    // ---- final l reduction across the quad ----
    l0 += __shfl_xor_sync(0xffffffffu, l0, 1);
    l0 += __shfl_xor_sync(0xffffffffu, l0, 2);
    l1 += __shfl_xor_sync(0xffffffffu, l1, 1);
    l1 += __shfl_xor_sync(0xffffffffu, l1, 2);

    // ---- stage normalized O (fp32, stride 132) and epilogue ----
    __syncthreads();
    float* Of = (float*)smh;
    const float inv0 = 1.f/l0, inv1 = 1.f/l1;
    #pragma unroll
    for (int cb = 0; cb < 16; cb++){
        *(float2*)(Of + srow*132 + cb*8 + 2*t4)     = make_float2(o[cb][0]*inv0, o[cb][1]*inv0);
        *(float2*)(Of + (srow+8)*132 + cb*8 + 2*t4) = make_float2(o[cb][2]*inv1, o[cb][3]*inv1);
    }
    __syncthreads();
    {
        const int row = tid>>1, half_ = tid&1;
        const int rowg = q0 + row;
        const float* Lp = gL + ((size_t)(b*1024) + rowg)*16;
        float Lq[16];
        #pragma unroll
        for (int i = 0; i < 4; i++){ float4 t4v = *(const float4*)(Lp + i*4);
            Lq[i*4+0]=t4v.x; Lq[i*4+1]=t4v.y; Lq[i*4+2]=t4v.z; Lq[i*4+3]=t4v.w; }
        const float* sp = Of + row*132 + half_*64;
        float* orow = gout + ((size_t)bh*Nn + rowg)*Cc + half_*64;
        #pragma unroll
        for (int g = 0; g < 16; g++){
            const int ch = half_*64 + g*4;
            float4 x = *(const float4*)(sp + g*4);
            float4 y;
            if (ch < 8) y = x;
            else {
                y.x = Lq[ 0]*x.x + Lq[ 1]*x.y + Lq[ 2]*x.z + Lq[ 3]*x.w;
                y.y = Lq[ 4]*x.x + Lq[ 5]*x.y + Lq[ 6]*x.z + Lq[ 7]*x.w;
                y.z = Lq[ 8]*x.x + Lq[ 9]*x.y + Lq[10]*x.z + Lq[11]*x.w;
                y.w = Lq[12]*x.x + Lq[13]*x.y + Lq[14]*x.z + Lq[15]*x.w;
            }
            *(float4*)(orow + g*4) = y;
        }
    }
}

extern "C" void kernel_launch(void* const* d_in, const int* in_sizes, int n_in,
                              void* d_out, int out_size)
{
    const float* q = (const float*)d_in[0];
    const float* k = (const float*)d_in[1];
    const float* v = (const float*)d_in[2];
    const float* L = (const float*)d_in[3];
    float* out = (float*)d_out;

    ipa_prep<<<512, 256>>>(q, k, v, L);

    cudaFuncSetAttribute(ipa_fa, cudaFuncAttributeMaxDynamicSharedMemorySize, 65536);
    dim3 grid(Nn/QT, 64);
    ipa_fa<<<grid, 128, 65536>>>(L, out);
}